// round 16
// baseline (speedup 1.0000x reference)
#include <cuda_runtime.h>
#include <cstdint>
#include <cstddef>

#define Bn   128
#define Sn   256
#define GM   (Bn*Sn)         // 32768
#define NEGV (-10000.0f)

typedef unsigned long long u64;

// ---------------- scratch (device globals; no allocation allowed) ----------------
__device__ float g_x  [GM*130];           // concat(word_emb, char_feat)
__device__ float g_wt [130*800];          // transposed input weights [k][n]
__device__ float g_pwt[200*32];           // transposed proj weights [k][tag]
__device__ float g_xw [2u*GM*400];        // x @ wih^T + (bih+bhh), per direction
__device__ float g_h  [2u*GM*100];        // hidden states f/b
__device__ float g_em [GM*32];            // emissions
__device__ float g_P  [100*96];           // char-conv table [c][k*32+f]

__device__ __forceinline__ float mtanh(float x){
    float r; asm("tanh.approx.f32 %0, %1;" : "=f"(r) : "f"(x)); return r;
}
__device__ __forceinline__ float msigm(float x){ return fmaf(mtanh(0.5f*x), 0.5f, 0.5f); }

// packed f32x2 helpers (Blackwell; ptxas never auto-fuses these)
__device__ __forceinline__ void fma2(u64 &d, u64 a, u64 b){
    asm("fma.rn.f32x2 %0, %1, %2, %0;" : "+l"(d) : "l"(a), "l"(b));
}
__device__ __forceinline__ u64 pack2(float x, float y){
    u64 r; asm("mov.b64 %0, {%1, %2};" : "=l"(r) : "f"(x), "f"(y)); return r;
}
__device__ __forceinline__ float2 unpack2(u64 v){
    float2 r; asm("mov.b64 {%0, %1}, %2;" : "=f"(r.x), "=f"(r.y) : "l"(v)); return r;
}

__device__ __forceinline__ uint32_t tf32cvt(float x){
    uint32_t r; asm("cvt.rna.tf32.f32 %0, %1;" : "=r"(r) : "f"(x)); return r;
}
__device__ __forceinline__ void mma_tf32(float* c,
    uint32_t a0, uint32_t a1, uint32_t a2, uint32_t a3, uint32_t b0, uint32_t b1)
{
    asm volatile("mma.sync.aligned.m16n8k8.row.col.f32.tf32.tf32.f32 "
        "{%0,%1,%2,%3}, {%4,%5,%6,%7}, {%8,%9}, {%0,%1,%2,%3};"
        : "+f"(c[0]), "+f"(c[1]), "+f"(c[2]), "+f"(c[3])
        : "r"(a0), "r"(a1), "r"(a2), "r"(a3), "r"(b0), "r"(b1));
}

// ---------------- kernel 0: prep = conv table + weight transposes ----------------
__global__ __launch_bounds__(256) void k_prep(
    const float* __restrict__ conv_w, const float* __restrict__ char_emb,
    const float* __restrict__ wih_f,  const float* __restrict__ wih_b,
    const float* __restrict__ proj_w)
{
    int idx = blockIdx.x*256 + threadIdx.x;
    if (idx < 9600){                              // P table: 100*96
        int c = idx / 96, r = idx % 96, k = r >> 5, f = r & 31;
        float s = 0.0f;
        if (f < 30){
            const float* w = conv_w + f*90 + k*30;
            const float* e = char_emb + c*30;
#pragma unroll
            for (int d=0; d<30; d++) s += w[d]*e[d];
        }
        g_P[idx] = s;
    }
    int idx2 = idx - 9600;                        // wt: 130*800
    if (idx2 >= 0 && idx2 < 130*800){
        int k = idx2 / 800, n = idx2 % 800;
        g_wt[idx2] = (n < 400) ? wih_f[(size_t)n*130 + k] : wih_b[(size_t)(n-400)*130 + k];
    }
    int idx3 = idx2 - 130*800;                    // pwt: 200*32
    if (idx3 >= 0 && idx3 < 6400){
        int k = idx3 >> 5, n = idx3 & 31;
        g_pwt[idx3] = proj_w[(size_t)n*200 + k];
    }
}

// ---------------- kernel 1: embedding concat + table-lookup char CNN -> g_x ----------------
__global__ __launch_bounds__(256) void k_cnn(
    const float* __restrict__ word_emb, const float* __restrict__ conv_b,
    const int*   __restrict__ word_x,   const int*   __restrict__ char_x)
{
    __shared__ float sP[9600];
    __shared__ float sb[32];

    int tid  = threadIdx.x;
    int lane = tid & 31;
    int wrp  = tid >> 5;

    for (int i = tid; i < 9600; i += 256) sP[i] = g_P[i];
    if (tid < 30) sb[tid] = conv_b[tid];
    __syncthreads();

    int base = blockIdx.x*64 + wrp*8;
#pragma unroll
    for (int i=0;i<8;i++){
        int bs = base + i;

        int cv = 0;
        if (lane < 10) cv = char_x[bs*10 + lane];

        int wid = word_x[bs];
        const float* wrow = word_emb + (size_t)wid*100;
        float* xo = g_x + (size_t)bs*130;
        for (int t = lane; t < 100; t += 32) xo[t] = wrow[t];

        int ci[10];
#pragma unroll
        for (int l=0;l<10;l++)
            ci[l] = __shfl_sync(0xffffffffu, cv, l)*96 + lane;

        float best = -1e30f;
#pragma unroll
        for (int p=0;p<12;p++){
            float acc = 0.0f;
            if (p >= 2)           acc += sP[ci[p-2] +  0];
            if (p >= 1 && p <=10) acc += sP[ci[p-1] + 32];
            if (p <= 9)           acc += sP[ci[p]   + 64];
            best = fmaxf(best, acc);
        }
        if (lane < 30) xo[100 + lane] = best + sb[lane];
    }
}

// ---------------- kernel 2: input-projection GEMM, tf32 mma.sync -> g_xw ----------------
__global__ __launch_bounds__(256,3) void k_gemm_in(
    const float* __restrict__ bih_f, const float* __restrict__ bhh_f,
    const float* __restrict__ bih_b, const float* __restrict__ bhh_b)
{
    __shared__ uint32_t As[128*36];   // 18.4 KB
    __shared__ uint32_t Bs[32*72];    //  9.2 KB

    int tid  = threadIdx.x;
    int m0   = blockIdx.y*128;
    int n0   = blockIdx.x*64;
    int w    = tid >> 5;
    int lane = tid & 31;
    int g    = lane >> 2, tg = lane & 3;
    int wm   = w >> 2,  wn = w & 3;    // 2 (m) x 4 (n) warps

    float acc[4][2][4];                // [mtile][ntile][c0..c3]
#pragma unroll
    for (int i=0;i<4;i++)
#pragma unroll
        for (int jj=0;jj<2;jj++)
#pragma unroll
            for (int q=0;q<4;q++) acc[i][jj][q] = 0.0f;

    for (int c=0; c<5; c++){
        int kb   = c*32;
        int klen = (c < 4) ? 32 : 2;

        for (int idx=tid; idx<128*32; idx+=256){
            int m = idx >> 5, k = idx & 31;
            float v = (k < klen) ? g_x[(size_t)(m0+m)*130 + kb + k] : 0.0f;
            As[m*36 + k] = tf32cvt(v);
        }
        for (int idx=tid; idx<32*64; idx+=256){
            int k = idx >> 6, n = idx & 63;
            int gn = n0 + n;
            float v = (k < klen && gn < 800) ? g_wt[(size_t)(kb+k)*800 + gn] : 0.0f;
            Bs[k*72 + n] = tf32cvt(v);
        }
        __syncthreads();

        int nks = (c < 4) ? 4 : 1;
#pragma unroll
        for (int ks=0; ks<4; ks++){
            if (ks >= nks) break;
            int k = ks*8;
            uint32_t af[4][4];
#pragma unroll
            for (int i=0;i<4;i++){
                int r0 = wm*64 + i*16 + g;
                af[i][0] = As[ r0    *36 + k + tg    ];
                af[i][1] = As[(r0+8) *36 + k + tg    ];
                af[i][2] = As[ r0    *36 + k + tg + 4];
                af[i][3] = As[(r0+8) *36 + k + tg + 4];
            }
            uint32_t bf[2][2];
#pragma unroll
            for (int jj=0;jj<2;jj++){
                int col = wn*16 + jj*8 + g;
                bf[jj][0] = Bs[(k + tg    )*72 + col];
                bf[jj][1] = Bs[(k + tg + 4)*72 + col];
            }
#pragma unroll
            for (int i=0;i<4;i++)
#pragma unroll
                for (int jj=0;jj<2;jj++)
                    mma_tf32(acc[i][jj], af[i][0], af[i][1], af[i][2], af[i][3],
                             bf[jj][0], bf[jj][1]);
        }
        __syncthreads();
    }

#pragma unroll
    for (int i=0;i<4;i++)
#pragma unroll
        for (int jj=0;jj<2;jj++){
            int m = m0 + wm*64 + i*16 + g;
            int n = n0 + wn*16 + jj*8 + tg*2;
            if (n < 800){
                int dir = n/400, j0 = n%400;
                float bia0 = dir ? (bih_b[j0  ]+bhh_b[j0  ]) : (bih_f[j0  ]+bhh_f[j0  ]);
                float bia1 = dir ? (bih_b[j0+1]+bhh_b[j0+1]) : (bih_f[j0+1]+bhh_f[j0+1]);
                float* d0 = g_xw + (size_t)dir*GM*400 + (size_t)m*400 + j0;
                *(float2*)d0            = make_float2(acc[i][jj][0]+bia0, acc[i][jj][1]+bia1);
                *(float2*)(d0 + 8*400)  = make_float2(acc[i][jj][2]+bia0, acc[i][jj][3]+bia1);
            }
        }
}

// ---------------- kernel 3: LSTM recurrence, K-split + xw prefetch -> g_h ----------------
// (Frozen at the measured local optimum: r11/r13 restructures both regressed.)
__global__ __launch_bounds__(800,1) void k_lstm(
    const float* __restrict__ whh_f, const float* __restrict__ whh_b)
{
    int bx  = blockIdx.x;
    int dir = bx >> 6;
    int pr  = bx & 63;
    int b0  = pr*2, b1 = b0+1;
    int tid = threadIdx.x;
    int half = (tid >= 400);
    int j    = half ? tid - 400 : tid;   // gate row 0..399
    int q0   = half ? 13 : 0;            // float4-group offset into h
    int nq   = half ? 12 : 13;
    int bmine = half ? b1 : b0;

    const float* whh = dir ? whh_b : whh_f;
    const ulonglong2* wrow = (const ulonglong2*)(whh + (size_t)j*100);
    ulonglong2 w[13];
#pragma unroll
    for (int q=0;q<13;q++){
        if (q < nq) w[q] = wrow[q0+q];
        else { w[q].x = 0ull; w[q].y = 0ull; }
    }

    __shared__ float h_s[2][112];     // zero-padded; group 25 reads land in zeros
    __shared__ float sp[2][2][400];   // [half][batch][gate]
    if (tid < 224) ((float*)h_s)[tid] = 0.0f;
    float c_reg = 0.0f;

    const float* xw   = g_xw + (size_t)dir*GM*400;
    float*       hout = g_h  + (size_t)dir*GM*100;
    __syncthreads();

    int t0 = dir ? 255 : 0;
    float av = xw[(size_t)(bmine*256+t0)*400 + j];

    for (int step=0; step<256; step++){
        int t = dir ? (255-step) : step;

        float nav = 0.0f;
        if (step < 255){
            int tn = dir ? (254-step) : (step+1);
            nav = xw[(size_t)(bmine*256+tn)*400 + j];
        }

        u64 s0=0ull, s0b=0ull, s1=0ull, s1b=0ull;
#pragma unroll
        for (int q=0;q<13;q++){
            ulonglong2 wq = w[q];
            ulonglong2 h0 = *(const ulonglong2*)&h_s[0][(q0+q)*4];
            ulonglong2 h1 = *(const ulonglong2*)&h_s[1][(q0+q)*4];
            fma2(s0,  wq.x, h0.x);
            fma2(s0b, wq.y, h0.y);
            fma2(s1,  wq.x, h1.x);
            fma2(s1b, wq.y, h1.y);
        }
        float2 u0 = unpack2(s0), u0b = unpack2(s0b);
        float2 u1 = unpack2(s1), u1b = unpack2(s1b);
        float d0 = (u0.x+u0.y)+(u0b.x+u0b.y);
        float d1 = (u1.x+u1.y)+(u1b.x+u1b.y);
        sp[half][0][j] = half ? d0 : d0 + av;
        sp[half][1][j] = half ? d1 + av : d1;
        __syncthreads();

        if (tid < 200){
            int bb = (tid >= 100), k = tid - bb*100;
            float gi = sp[0][bb][k]     + sp[1][bb][k];
            float gf = sp[0][bb][100+k] + sp[1][bb][100+k];
            float gg = sp[0][bb][200+k] + sp[1][bb][200+k];
            float go = sp[0][bb][300+k] + sp[1][bb][300+k];
            float ct = msigm(gf)*c_reg + msigm(gi)*mtanh(gg);
            c_reg = ct;
            float h = msigm(go)*mtanh(ct);
            h_s[bb][k] = h;
            hout[(size_t)((bb?b1:b0)*256+t)*100 + k] = h;
        }
        __syncthreads();
        av = nav;
    }
}

// ---------------- kernel 4: emission projection, tf32 mma.sync -> g_em ----------------
// [32768 x 200] @ [200 x 32]. Block = 128 rows, 8 warps (warp = 16 rows x 32 tags).
// A smem [m][k] stride 36; B smem [k][tag] width 40 (bank (8tg+g)%32, conflict-free).
__global__ __launch_bounds__(256) void k_emis(const float* __restrict__ proj_b)
{
    __shared__ uint32_t As[128*36];
    __shared__ uint32_t Bs[32*40];
    __shared__ float pb[32];

    int tid  = threadIdx.x;
    int m0   = blockIdx.x*128;
    int w    = tid >> 5;
    int lane = tid & 31;
    int g    = lane >> 2, tg = lane & 3;

    if (tid < 32) pb[tid] = proj_b[tid];

    float acc[4][4];
#pragma unroll
    for (int jj=0;jj<4;jj++)
#pragma unroll
        for (int q=0;q<4;q++) acc[jj][q] = 0.0f;

    for (int c=0; c<7; c++){
        int kb = c*32;

        for (int idx=tid; idx<128*32; idx+=256){
            int m = idx >> 5, k = idx & 31;
            int kk = kb + k;
            float v = 0.0f;
            if (kk < 100)       v = g_h[(size_t)(m0+m)*100 + kk];
            else if (kk < 200)  v = g_h[(size_t)GM*100 + (size_t)(m0+m)*100 + (kk-100)];
            As[m*36 + k] = tf32cvt(v);
        }
        for (int idx=tid; idx<32*32; idx+=256){
            int k = idx >> 5, n = idx & 31;
            int kk = kb + k;
            float v = (kk < 200) ? g_pwt[kk*32 + n] : 0.0f;
            Bs[k*40 + n] = tf32cvt(v);
        }
        __syncthreads();

        int nks = (c < 6) ? 4 : 1;
#pragma unroll
        for (int ks=0; ks<4; ks++){
            if (ks >= nks) break;
            int k = ks*8;
            int r0 = w*16 + g;
            uint32_t a0 = As[ r0    *36 + k + tg    ];
            uint32_t a1 = As[(r0+8) *36 + k + tg    ];
            uint32_t a2 = As[ r0    *36 + k + tg + 4];
            uint32_t a3 = As[(r0+8) *36 + k + tg + 4];
#pragma unroll
            for (int jj=0;jj<4;jj++){
                uint32_t b0 = Bs[(k + tg    )*40 + jj*8 + g];
                uint32_t b1 = Bs[(k + tg + 4)*40 + jj*8 + g];
                mma_tf32(acc[jj], a0, a1, a2, a3, b0, b1);
            }
        }
        __syncthreads();
    }

#pragma unroll
    for (int jj=0;jj<4;jj++){
        int m = m0 + w*16 + g;
        int n = jj*8 + tg*2;
        float b0 = pb[n], b1 = pb[n+1];
        *(float2*)&g_em[(size_t)m*32 + n]     = make_float2(acc[jj][0]+b0, acc[jj][1]+b1);
        *(float2*)&g_em[(size_t)(m+8)*32 + n] = make_float2(acc[jj][2]+b0, acc[jj][3]+b1);
    }
}

// ---------------- kernel 5: CRF, linear-domain forward (exp/log off the chain) ----------------
// L_j <- (sum_i L_i * T_ij) * e^{em_j}; renormalize by lane0 every 8 steps.
// Growth <= ~50x/step, spread <= e^25 -> max ~3e24 < FLT_MAX. Lane START: T col = 0 -> L=0 exact.
__global__ __launch_bounds__(32) void k_crf(
    const float* __restrict__ trans, const int* __restrict__ y, float* __restrict__ out)
{
    __shared__ float E_s[32];
    int j = threadIdx.x, b = blockIdx.x;

    float T[32];
#pragma unroll
    for (int i=0;i<32;i++) T[i] = __expf(trans[i*32 + j]);   // exp(NEG)=0, safe
    float tend = trans[j*32 + 31];                           // trans[j, END]

    float score = 0.0f;
    for (int t=j; t<256; t+=32){
        int cur  = y[b*256+t];
        int prev = (t==0) ? 30 : y[b*256+t-1];
        score += g_em[(size_t)(b*256+t)*32 + cur] + trans[prev*32+cur];
    }
    __syncwarp();

    // init (t=0 closed form), normalized to lane0
    float la1 = g_em[(size_t)(b*256)*32 + j] + trans[30*32 + j];
    float m0  = __shfl_sync(0xffffffffu, la1, 0);
    float L   = __expf(la1 - m0);
    float logacc = m0;

    float emexp = __expf(g_em[(size_t)(b*256+1)*32 + j]);

    for (int t=1; t<256; t++){
        // prefetch next emission and do its exp off the critical chain
        float emn = (t < 255) ? g_em[(size_t)(b*256+t+1)*32 + j] : 0.0f;
        float emexp_n = __expf(emn);

        E_s[j] = L;
        __syncwarp();
        float s0=0.f, s1=0.f, s2=0.f, s3=0.f;
#pragma unroll
        for (int i=0;i<8;i++){
            s0 += E_s[i   ]*T[i   ];
            s1 += E_s[i+ 8]*T[i+ 8];
            s2 += E_s[i+16]*T[i+16];
            s3 += E_s[i+24]*T[i+24];
        }
        L = ((s0+s1)+(s2+s3)) * emexp;
        __syncwarp();

        if ((t & 7) == 0){
            float f = __shfl_sync(0xffffffffu, L, 0);   // >0 (col 0 is not START)
            L *= (1.0f/f);
            logacc += __logf(f);
        }
        emexp = emexp_n;
    }

    // total = logacc + log( sum_j L_j * e^{tend_j} )   (e^{NEG} = 0 handles END row)
    float v = L * __expf(tend);
#pragma unroll
    for (int o=16;o>0;o>>=1) v += __shfl_xor_sync(0xffffffffu, v, o);
    float total = logacc + __logf(v);

#pragma unroll
    for (int o=16;o>0;o>>=1) score += __shfl_xor_sync(0xffffffffu, score, o);

    if (j==0){
        score += trans[y[b*256+255]*32 + 31];
        atomicAdd(out, (total - score) * (1.0f/128.0f));
    }
}

// ---------------- launch ----------------
extern "C" void kernel_launch(void* const* d_in, const int* in_sizes, int n_in,
                              void* d_out, int out_size)
{
    const float* word_emb = (const float*)d_in[0];
    const float* char_emb = (const float*)d_in[1];
    const float* conv_w   = (const float*)d_in[2];
    const float* conv_b   = (const float*)d_in[3];
    const float* wih_f    = (const float*)d_in[4];
    const float* whh_f    = (const float*)d_in[5];
    const float* bih_f    = (const float*)d_in[6];
    const float* bhh_f    = (const float*)d_in[7];
    const float* wih_b    = (const float*)d_in[8];
    const float* whh_b    = (const float*)d_in[9];
    const float* bih_b    = (const float*)d_in[10];
    const float* bhh_b    = (const float*)d_in[11];
    const float* proj_w   = (const float*)d_in[12];
    const float* proj_b   = (const float*)d_in[13];
    const float* trans    = (const float*)d_in[14];
    const int*   word_x   = (const int*)d_in[15];
    const int*   char_x   = (const int*)d_in[16];
    const int*   y        = (const int*)d_in[17];
    float* out = (float*)d_out;

    k_prep<<<(9600+130*800+6400+255)/256,256>>>(conv_w, char_emb, wih_f, wih_b, proj_w);
    k_cnn<<<512,256>>>(word_emb, conv_b, word_x, char_x);
    dim3 gg(13, 256);
    k_gemm_in<<<gg,256>>>(bih_f, bhh_f, bih_b, bhh_b);
    k_lstm<<<128,800>>>(whh_f, whh_b);
    k_emis<<<256,256>>>(proj_b);
    cudaMemsetAsync(out, 0, sizeof(float));
    k_crf<<<128,32>>>(trans, y, out);
}

// round 17
// speedup vs baseline: 1.0453x; 1.0453x over previous
#include <cuda_runtime.h>
#include <cstdint>
#include <cstddef>

#define Bn   128
#define Sn   256
#define GM   (Bn*Sn)         // 32768
#define NEGV (-10000.0f)

typedef unsigned long long u64;

// ---------------- scratch (device globals; no allocation allowed) ----------------
__device__ float g_x [GM*130];            // concat(word_emb, char_feat)
__device__ float g_wt[130*800];           // transposed input weights [k][n]
__device__ float g_xw[2u*GM*400];         // x @ wih^T + (bih+bhh), per direction
__device__ float g_h [2u*GM*100];         // hidden states f/b
__device__ float g_em[GM*32];             // emissions
__device__ float g_P [100*96];            // char-conv table [c][k*32+f]

__device__ __forceinline__ float mtanh(float x){
    float r; asm("tanh.approx.f32 %0, %1;" : "=f"(r) : "f"(x)); return r;
}
__device__ __forceinline__ float msigm(float x){ return fmaf(mtanh(0.5f*x), 0.5f, 0.5f); }

// packed f32x2 helpers (Blackwell; ptxas never auto-fuses these)
__device__ __forceinline__ void fma2(u64 &d, u64 a, u64 b){
    asm("fma.rn.f32x2 %0, %1, %2, %0;" : "+l"(d) : "l"(a), "l"(b));
}
__device__ __forceinline__ u64 pack2(float x, float y){
    u64 r; asm("mov.b64 %0, {%1, %2};" : "=l"(r) : "f"(x), "f"(y)); return r;
}
__device__ __forceinline__ float2 unpack2(u64 v){
    float2 r; asm("mov.b64 {%0, %1}, %2;" : "=f"(r.x), "=f"(r.y) : "l"(v)); return r;
}

__device__ __forceinline__ uint32_t tf32cvt(float x){
    uint32_t r; asm("cvt.rna.tf32.f32 %0, %1;" : "=r"(r) : "f"(x)); return r;
}
__device__ __forceinline__ void mma_tf32(float* c,
    uint32_t a0, uint32_t a1, uint32_t a2, uint32_t a3, uint32_t b0, uint32_t b1)
{
    asm volatile("mma.sync.aligned.m16n8k8.row.col.f32.tf32.tf32.f32 "
        "{%0,%1,%2,%3}, {%4,%5,%6,%7}, {%8,%9}, {%0,%1,%2,%3};"
        : "+f"(c[0]), "+f"(c[1]), "+f"(c[2]), "+f"(c[3])
        : "r"(a0), "r"(a1), "r"(a2), "r"(a3), "r"(b0), "r"(b1));
}

// ---------------- kernel 0: prep = char-conv table + weight transpose ----------------
__global__ __launch_bounds__(256) void k_prep(
    const float* __restrict__ conv_w, const float* __restrict__ char_emb,
    const float* __restrict__ wih_f,  const float* __restrict__ wih_b)
{
    int idx = blockIdx.x*256 + threadIdx.x;
    if (idx < 9600){                              // P table: 100*96
        int c = idx / 96, r = idx % 96, k = r >> 5, f = r & 31;
        float s = 0.0f;
        if (f < 30){
            const float* w = conv_w + f*90 + k*30;
            const float* e = char_emb + c*30;
#pragma unroll
            for (int d=0; d<30; d++) s += w[d]*e[d];
        }
        g_P[idx] = s;
    }
    int idx2 = idx - 9600;                        // wt: 130*800
    if (idx2 >= 0 && idx2 < 130*800){
        int k = idx2 / 800, n = idx2 % 800;
        g_wt[idx2] = (n < 400) ? wih_f[(size_t)n*130 + k] : wih_b[(size_t)(n-400)*130 + k];
    }
}

// ---------------- kernel 1: embedding concat + table-lookup char CNN -> g_x ----------------
__global__ __launch_bounds__(256) void k_cnn(
    const float* __restrict__ word_emb, const float* __restrict__ conv_b,
    const int*   __restrict__ word_x,   const int*   __restrict__ char_x)
{
    __shared__ float sP[9600];
    __shared__ float sb[32];

    int tid  = threadIdx.x;
    int lane = tid & 31;
    int wrp  = tid >> 5;

    for (int i = tid; i < 9600; i += 256) sP[i] = g_P[i];
    if (tid < 30) sb[tid] = conv_b[tid];
    __syncthreads();

    int base = blockIdx.x*64 + wrp*8;
#pragma unroll
    for (int i=0;i<8;i++){
        int bs = base + i;

        int cv = 0;
        if (lane < 10) cv = char_x[bs*10 + lane];

        int wid = word_x[bs];
        const float* wrow = word_emb + (size_t)wid*100;
        float* xo = g_x + (size_t)bs*130;
        for (int t = lane; t < 100; t += 32) xo[t] = wrow[t];

        int ci[10];
#pragma unroll
        for (int l=0;l<10;l++)
            ci[l] = __shfl_sync(0xffffffffu, cv, l)*96 + lane;

        float best = -1e30f;
#pragma unroll
        for (int p=0;p<12;p++){
            float acc = 0.0f;
            if (p >= 2)           acc += sP[ci[p-2] +  0];
            if (p >= 1 && p <=10) acc += sP[ci[p-1] + 32];
            if (p <= 9)           acc += sP[ci[p]   + 64];
            best = fmaxf(best, acc);
        }
        if (lane < 30) xo[100 + lane] = best + sb[lane];
    }
}

// ---------------- kernel 2: input-projection GEMM, tf32 mma.sync -> g_xw ----------------
__global__ __launch_bounds__(256,3) void k_gemm_in(
    const float* __restrict__ bih_f, const float* __restrict__ bhh_f,
    const float* __restrict__ bih_b, const float* __restrict__ bhh_b)
{
    __shared__ uint32_t As[128*36];   // 18.4 KB
    __shared__ uint32_t Bs[32*72];    //  9.2 KB

    int tid  = threadIdx.x;
    int m0   = blockIdx.y*128;
    int n0   = blockIdx.x*64;
    int w    = tid >> 5;
    int lane = tid & 31;
    int g    = lane >> 2, tg = lane & 3;
    int wm   = w >> 2,  wn = w & 3;    // 2 (m) x 4 (n) warps

    float acc[4][2][4];                // [mtile][ntile][c0..c3]
#pragma unroll
    for (int i=0;i<4;i++)
#pragma unroll
        for (int jj=0;jj<2;jj++)
#pragma unroll
            for (int q=0;q<4;q++) acc[i][jj][q] = 0.0f;

    for (int c=0; c<5; c++){
        int kb   = c*32;
        int klen = (c < 4) ? 32 : 2;

        for (int idx=tid; idx<128*32; idx+=256){
            int m = idx >> 5, k = idx & 31;
            float v = (k < klen) ? g_x[(size_t)(m0+m)*130 + kb + k] : 0.0f;
            As[m*36 + k] = tf32cvt(v);
        }
        for (int idx=tid; idx<32*64; idx+=256){
            int k = idx >> 6, n = idx & 63;
            int gn = n0 + n;
            float v = (k < klen && gn < 800) ? g_wt[(size_t)(kb+k)*800 + gn] : 0.0f;
            Bs[k*72 + n] = tf32cvt(v);
        }
        __syncthreads();

        int nks = (c < 4) ? 4 : 1;
#pragma unroll
        for (int ks=0; ks<4; ks++){
            if (ks >= nks) break;
            int k = ks*8;
            uint32_t af[4][4];
#pragma unroll
            for (int i=0;i<4;i++){
                int r0 = wm*64 + i*16 + g;
                af[i][0] = As[ r0    *36 + k + tg    ];
                af[i][1] = As[(r0+8) *36 + k + tg    ];
                af[i][2] = As[ r0    *36 + k + tg + 4];
                af[i][3] = As[(r0+8) *36 + k + tg + 4];
            }
            uint32_t bf[2][2];
#pragma unroll
            for (int jj=0;jj<2;jj++){
                int col = wn*16 + jj*8 + g;
                bf[jj][0] = Bs[(k + tg    )*72 + col];
                bf[jj][1] = Bs[(k + tg + 4)*72 + col];
            }
#pragma unroll
            for (int i=0;i<4;i++)
#pragma unroll
                for (int jj=0;jj<2;jj++)
                    mma_tf32(acc[i][jj], af[i][0], af[i][1], af[i][2], af[i][3],
                             bf[jj][0], bf[jj][1]);
        }
        __syncthreads();
    }

#pragma unroll
    for (int i=0;i<4;i++)
#pragma unroll
        for (int jj=0;jj<2;jj++){
            int m = m0 + wm*64 + i*16 + g;
            int n = n0 + wn*16 + jj*8 + tg*2;
            if (n < 800){
                int dir = n/400, j0 = n%400;
                float bia0 = dir ? (bih_b[j0  ]+bhh_b[j0  ]) : (bih_f[j0  ]+bhh_f[j0  ]);
                float bia1 = dir ? (bih_b[j0+1]+bhh_b[j0+1]) : (bih_f[j0+1]+bhh_f[j0+1]);
                float* d0 = g_xw + (size_t)dir*GM*400 + (size_t)m*400 + j0;
                *(float2*)d0            = make_float2(acc[i][jj][0]+bia0, acc[i][jj][1]+bia1);
                *(float2*)(d0 + 8*400)  = make_float2(acc[i][jj][2]+bia0, acc[i][jj][3]+bia1);
            }
        }
}

// ---------------- kernel 3: LSTM recurrence, K-split + xw prefetch -> g_h ----------------
// (Frozen at the measured local optimum: r11/r13 restructures both regressed.)
__global__ __launch_bounds__(800,1) void k_lstm(
    const float* __restrict__ whh_f, const float* __restrict__ whh_b)
{
    int bx  = blockIdx.x;
    int dir = bx >> 6;
    int pr  = bx & 63;
    int b0  = pr*2, b1 = b0+1;
    int tid = threadIdx.x;
    int half = (tid >= 400);
    int j    = half ? tid - 400 : tid;   // gate row 0..399
    int q0   = half ? 13 : 0;            // float4-group offset into h
    int nq   = half ? 12 : 13;
    int bmine = half ? b1 : b0;

    const float* whh = dir ? whh_b : whh_f;
    const ulonglong2* wrow = (const ulonglong2*)(whh + (size_t)j*100);
    ulonglong2 w[13];
#pragma unroll
    for (int q=0;q<13;q++){
        if (q < nq) w[q] = wrow[q0+q];
        else { w[q].x = 0ull; w[q].y = 0ull; }
    }

    __shared__ float h_s[2][112];     // zero-padded; group 25 reads land in zeros
    __shared__ float sp[2][2][400];   // [half][batch][gate]
    if (tid < 224) ((float*)h_s)[tid] = 0.0f;
    float c_reg = 0.0f;

    const float* xw   = g_xw + (size_t)dir*GM*400;
    float*       hout = g_h  + (size_t)dir*GM*100;
    __syncthreads();

    int t0 = dir ? 255 : 0;
    float av = xw[(size_t)(bmine*256+t0)*400 + j];

    for (int step=0; step<256; step++){
        int t = dir ? (255-step) : step;

        float nav = 0.0f;
        if (step < 255){
            int tn = dir ? (254-step) : (step+1);
            nav = xw[(size_t)(bmine*256+tn)*400 + j];
        }

        u64 s0=0ull, s0b=0ull, s1=0ull, s1b=0ull;
#pragma unroll
        for (int q=0;q<13;q++){
            ulonglong2 wq = w[q];
            ulonglong2 h0 = *(const ulonglong2*)&h_s[0][(q0+q)*4];
            ulonglong2 h1 = *(const ulonglong2*)&h_s[1][(q0+q)*4];
            fma2(s0,  wq.x, h0.x);
            fma2(s0b, wq.y, h0.y);
            fma2(s1,  wq.x, h1.x);
            fma2(s1b, wq.y, h1.y);
        }
        float2 u0 = unpack2(s0), u0b = unpack2(s0b);
        float2 u1 = unpack2(s1), u1b = unpack2(s1b);
        float d0 = (u0.x+u0.y)+(u0b.x+u0b.y);
        float d1 = (u1.x+u1.y)+(u1b.x+u1b.y);
        sp[half][0][j] = half ? d0 : d0 + av;
        sp[half][1][j] = half ? d1 + av : d1;
        __syncthreads();

        if (tid < 200){
            int bb = (tid >= 100), k = tid - bb*100;
            float gi = sp[0][bb][k]     + sp[1][bb][k];
            float gf = sp[0][bb][100+k] + sp[1][bb][100+k];
            float gg = sp[0][bb][200+k] + sp[1][bb][200+k];
            float go = sp[0][bb][300+k] + sp[1][bb][300+k];
            float ct = msigm(gf)*c_reg + msigm(gi)*mtanh(gg);
            c_reg = ct;
            float h = msigm(go)*mtanh(ct);
            h_s[bb][k] = h;
            hout[(size_t)((bb?b1:b0)*256+t)*100 + k] = h;
        }
        __syncthreads();
        av = nav;
    }
}

// ---------------- kernel 4: emission projection (tiled, scalar) -> g_em ----------------
__global__ __launch_bounds__(256) void k_emis(
    const float* __restrict__ proj_w, const float* __restrict__ proj_b)
{
    __shared__ float hs[64*204];   // [m][k] padded row stride
    __shared__ float pw[200*32];   // [k][tag]
    __shared__ float pb[32];

    int tid = threadIdx.x;
    int bs0 = blockIdx.x*64;

    for (int idx=tid; idx<6400; idx+=256){
        int tag = idx/200, k = idx%200;
        pw[k*32+tag] = proj_w[idx];
    }
    if (tid < 32) pb[tid] = proj_b[tid];

    for (int idx=tid; idx<64*50; idx+=256){
        int m = idx/50, q = idx%50;
        int bs = bs0 + m;
        const float* src = (q < 25) ? (g_h + (size_t)bs*100 + q*4)
                                    : (g_h + (size_t)GM*100 + (size_t)bs*100 + (q-25)*4);
        float4 v = *(const float4*)src;
        *(float4*)&hs[m*204 + q*4] = v;
    }
    __syncthreads();

    int tag  = tid & 31;
    int msub = tid >> 5;           // 0..7

    float acc[8];
#pragma unroll
    for (int i=0;i<8;i++) acc[i] = pb[tag];

    for (int k=0;k<200;k++){
        float pwv = pw[k*32 + tag];
#pragma unroll
        for (int i=0;i<8;i++)
            acc[i] += hs[(msub + 8*i)*204 + k] * pwv;   // broadcast read
    }
#pragma unroll
    for (int i=0;i<8;i++)
        g_em[(size_t)(bs0 + msub + 8*i)*32 + tag] = acc[i];
}

// ---------------- kernel 5: CRF, linear-domain forward (exp/log off the chain) ----------------
// L_j <- (sum_i L_i * T_ij) * e^{em_j}; renormalize by lane0 every 8 steps.
// Growth <= ~50x/step, spread bounded -> no overflow within 8 steps. Lane START col of T = 0 -> exact.
__global__ __launch_bounds__(32) void k_crf(
    const float* __restrict__ trans, const int* __restrict__ y, float* __restrict__ out)
{
    __shared__ float E_s[32];
    int j = threadIdx.x, b = blockIdx.x;

    float T[32];
#pragma unroll
    for (int i=0;i<32;i++) T[i] = __expf(trans[i*32 + j]);   // exp(NEG)=0, safe
    float tend = trans[j*32 + 31];                           // trans[j, END]

    float score = 0.0f;
    for (int t=j; t<256; t+=32){
        int cur  = y[b*256+t];
        int prev = (t==0) ? 30 : y[b*256+t-1];
        score += g_em[(size_t)(b*256+t)*32 + cur] + trans[prev*32+cur];
    }
    __syncwarp();

    // init (t=0 closed form), normalized to lane0
    float la1 = g_em[(size_t)(b*256)*32 + j] + trans[30*32 + j];
    float m0  = __shfl_sync(0xffffffffu, la1, 0);
    float L   = __expf(la1 - m0);
    float logacc = m0;

    float emexp = __expf(g_em[(size_t)(b*256+1)*32 + j]);

    for (int t=1; t<256; t++){
        // prefetch next emission and do its exp off the critical chain
        float emn = (t < 255) ? g_em[(size_t)(b*256+t+1)*32 + j] : 0.0f;
        float emexp_n = __expf(emn);

        E_s[j] = L;
        __syncwarp();
        float s0=0.f, s1=0.f, s2=0.f, s3=0.f;
#pragma unroll
        for (int i=0;i<8;i++){
            s0 += E_s[i   ]*T[i   ];
            s1 += E_s[i+ 8]*T[i+ 8];
            s2 += E_s[i+16]*T[i+16];
            s3 += E_s[i+24]*T[i+24];
        }
        L = ((s0+s1)+(s2+s3)) * emexp;
        __syncwarp();

        if ((t & 7) == 0){
            float f = __shfl_sync(0xffffffffu, L, 0);   // >0 (col 0 is not START)
            L *= (1.0f/f);
            logacc += __logf(f);
        }
        emexp = emexp_n;
    }

    // total = logacc + log( sum_j L_j * e^{tend_j} )   (e^{NEG} = 0 handles END row)
    float v = L * __expf(tend);
#pragma unroll
    for (int o=16;o>0;o>>=1) v += __shfl_xor_sync(0xffffffffu, v, o);
    float total = logacc + __logf(v);

#pragma unroll
    for (int o=16;o>0;o>>=1) score += __shfl_xor_sync(0xffffffffu, score, o);

    if (j==0){
        score += trans[y[b*256+255]*32 + 31];
        atomicAdd(out, (total - score) * (1.0f/128.0f));
    }
}

// ---------------- launch ----------------
extern "C" void kernel_launch(void* const* d_in, const int* in_sizes, int n_in,
                              void* d_out, int out_size)
{
    const float* word_emb = (const float*)d_in[0];
    const float* char_emb = (const float*)d_in[1];
    const float* conv_w   = (const float*)d_in[2];
    const float* conv_b   = (const float*)d_in[3];
    const float* wih_f    = (const float*)d_in[4];
    const float* whh_f    = (const float*)d_in[5];
    const float* bih_f    = (const float*)d_in[6];
    const float* bhh_f    = (const float*)d_in[7];
    const float* wih_b    = (const float*)d_in[8];
    const float* whh_b    = (const float*)d_in[9];
    const float* bih_b    = (const float*)d_in[10];
    const float* bhh_b    = (const float*)d_in[11];
    const float* proj_w   = (const float*)d_in[12];
    const float* proj_b   = (const float*)d_in[13];
    const float* trans    = (const float*)d_in[14];
    const int*   word_x   = (const int*)d_in[15];
    const int*   char_x   = (const int*)d_in[16];
    const int*   y        = (const int*)d_in[17];
    float* out = (float*)d_out;

    k_prep<<<(9600+130*800+255)/256,256>>>(conv_w, char_emb, wih_f, wih_b);
    k_cnn<<<512,256>>>(word_emb, conv_b, word_x, char_x);
    dim3 gg(13, 256);
    k_gemm_in<<<gg,256>>>(bih_f, bhh_f, bih_b, bhh_b);
    k_lstm<<<128,800>>>(whh_f, whh_b);
    k_emis<<<512,256>>>(proj_w, proj_b);
    cudaMemsetAsync(out, 0, sizeof(float));
    k_crf<<<128,32>>>(trans, y, out);
}